// round 16
// baseline (speedup 1.0000x reference)
#include <cuda_runtime.h>
#include <cuda_bf16.h>
#include <math.h>

#define Bz 4
#define Cc 64
#define Hh 96
#define Ww 384
#define BHn (Bz*Hh)
#define NX (Bz*Cc*Hh*Ww)
#define NLR (Bz*3*Hh*Ww)
#define EPS 1e-6f

typedef unsigned long long u64;
typedef unsigned int u32;
typedef unsigned short u16;
__device__ __forceinline__ u64 dup2f(float x) {
    u64 r; asm("mov.b64 %0, {%1, %1};" : "=l"(r) : "f"(x)); return r;
}
__device__ __forceinline__ void fma2(u64 &d, u64 a, u64 b) {
    asm("fma.rn.f32x2 %0, %1, %2, %0;" : "+l"(d) : "l"(a), "l"(b));
}
__device__ __forceinline__ float2 up2(u64 v) {
    float2 r; asm("mov.b64 {%0, %1}, %2;" : "=f"(r.x), "=f"(r.y) : "l"(v)); return r;
}
__device__ __forceinline__ u32 smem_u32(const void* p) {
    u32 a; asm("{ .reg .u64 t; cvta.to.shared.u64 t, %1; cvt.u32.u64 %0, t; }" : "=r"(a) : "l"(p));
    return a;
}
__device__ __forceinline__ void unp4(uint2 p, float* f) {
    __nv_bfloat162 a = *(__nv_bfloat162*)&p.x;
    __nv_bfloat162 b = *(__nv_bfloat162*)&p.y;
    f[0] = __bfloat162float(a.x); f[1] = __bfloat162float(a.y);
    f[2] = __bfloat162float(b.x); f[3] = __bfloat162float(b.y);
}
__device__ __forceinline__ uint2 pack4bf(float a, float b, float c, float d) {
    __nv_bfloat162 p0 = __floats2bfloat162_rn(a, b);
    __nv_bfloat162 p1 = __floats2bfloat162_rn(c, d);
    uint2 r;
    r.x = *(u32*)&p0; r.y = *(u32*)&p1;
    return r;
}

__device__ __align__(16) __nv_bfloat16 b_Q[2][BHn][Ww][Cc];
__device__ __align__(16) __nv_bfloat16 b_A[BHn][Ww][Ww];
__device__ __align__(16) __nv_bfloat16 b_Mr2l[BHn][Ww][Ww];
__device__ __align__(16) __nv_bfloat16 b_MLT[BHn][Ww][Ww];
__device__ __align__(16) __nv_bfloat16 b_Mr2lT[BHn][Ww][Ww];
__device__ __align__(16) __nv_bfloat16 b_MLTT[BHn][Ww][Ww];
__device__ __align__(16) __nv_bfloat16 b_VT[2][BHn][Cc][Ww];
__device__ __align__(16) float g_rmax[BHn][Ww];
__device__ __align__(16) float g_rinv[BHn][Ww];
__device__ __align__(16) float g_cmax[BHn][Ww];
__device__ __align__(16) float g_cinv[BHn][Ww];
__device__ __align__(16) float g_ms_r2l[BHn][Ww];
__device__ __align__(16) float g_ms_l2r[BHn][Ww];

#define NP_CYC (2*BHn*9)
#define NP_PH1 (48*BHn)
#define NP_PH2 (BHn)
#define NP_SM  (2*BHn*24)
__device__ float g_p_cyc[NP_CYC];
__device__ float g_p_ph1[NP_PH1];
__device__ float g_p_ph2[NP_PH2];
__device__ float g_p_smh[NP_SM];
__device__ float g_p_smw[NP_SM];

// ====== K1: LN + both 1x1 projections, FFMA2, both sides in one launch ======
#define PIX 192
__global__ void k1_lnproj(const float* __restrict__ x_l, const float* __restrict__ x_r,
                          const float* __restrict__ nlw, const float* __restrict__ nlb,
                          const float* __restrict__ nrw, const float* __restrict__ nrb,
                          const float* __restrict__ lp1w, const float* __restrict__ lp1b,
                          const float* __restrict__ rp1w, const float* __restrict__ rp1b,
                          const float* __restrict__ lp2w, const float* __restrict__ lp2b,
                          const float* __restrict__ rp2w, const float* __restrict__ rp2b)
{
    extern __shared__ float sm[];
    float* xs   = sm;
    float* w1   = xs + Cc*PIX;
    float* w2   = w1 + Cc*Cc;
    float* s1   = w2 + Cc*Cc;
    float* t1   = s1 + Cc;
    float* mval = t1 + Cc;
    float* rval = mval + PIX;

    const int side = blockIdx.z;
    const float* __restrict__ x  = side ? x_r : x_l;
    const float* __restrict__ nw = side ? nrw : nlw;
    const float* __restrict__ nb = side ? nrb : nlb;
    const float* __restrict__ p1 = side ? rp1w : lp1w;
    const float* __restrict__ b1 = side ? rp1b : lp1b;
    const float* __restrict__ p2 = side ? rp2w : lp2w;
    const float* __restrict__ b2 = side ? rp2b : lp2b;

    const int bh = blockIdx.y;
    const int b = bh / Hh, h = bh % Hh;
    const int w0 = blockIdx.x * PIX;
    const int tid = threadIdx.x;

    for (int idx = tid; idx < Cc*Cc; idx += 256) {
        int c = idx & 63;
        w1[idx] = p1[idx] * nw[c];
        w2[idx] = p2[idx];
    }
    for (int idx = tid; idx < Cc*PIX; idx += 256) {
        int c = idx / PIX, p = idx % PIX;
        xs[idx] = x[(((long)b*Cc + c)*Hh + h)*Ww + w0 + p];
    }
    __syncthreads();

    for (int o = tid; o < Cc; o += 256) {
        float s = 0.f, t = b1[o];
        for (int c = 0; c < Cc; c++) { s += w1[o*Cc + c]; t += p1[o*Cc + c]*nb[c]; }
        s1[o] = s; t1[o] = t;
    }
    for (int p = tid; p < PIX; p += 256) {
        float s = 0.f, q = 0.f;
        for (int c = 0; c < Cc; c++) { float v = xs[c*PIX + p]; s += v; q += v*v; }
        float mu = s * (1.f/Cc);
        float var = q*(1.f/Cc) - mu*mu;
        float r = rsqrtf(var + EPS);
        rval[p] = r; mval[p] = -r*mu;
    }
    __syncthreads();

    const int tx = tid & 15, ty = tid >> 4;
    u64 acc2[4][6];
    float so[4], to[4];
    #pragma unroll
    for (int i = 0; i < 4; i++) { so[i] = s1[ty*4+i]; to[i] = t1[ty*4+i]; }

    #pragma unroll
    for (int i = 0; i < 4; i++)
        #pragma unroll
        for (int j = 0; j < 6; j++) acc2[i][j] = 0ULL;
    for (int c = 0; c < Cc; c++) {
        float4 wv = make_float4(w1[(ty*4+0)*Cc+c], w1[(ty*4+1)*Cc+c],
                                w1[(ty*4+2)*Cc+c], w1[(ty*4+3)*Cc+c]);
        u64 A0 = dup2f(wv.x), A1 = dup2f(wv.y), A2 = dup2f(wv.z), A3 = dup2f(wv.w);
        #pragma unroll
        for (int j = 0; j < 6; j++) {
            u64 X = *(const u64*)&xs[c*PIX + 2*tx + 32*j];
            fma2(acc2[0][j], A0, X); fma2(acc2[1][j], A1, X);
            fma2(acc2[2][j], A2, X); fma2(acc2[3][j], A3, X);
        }
    }
    #pragma unroll
    for (int j = 0; j < 6; j++) {
        int p = 2*tx + 32*j;
        float2 f0 = up2(acc2[0][j]), f1 = up2(acc2[1][j]);
        float2 f2 = up2(acc2[2][j]), f3 = up2(acc2[3][j]);
        float r0 = rval[p], m0 = mval[p], r1 = rval[p+1], m1 = mval[p+1];
        *(uint2*)&b_Q[side][bh][w0+p][ty*4] =
            pack4bf(r0*f0.x + m0*so[0] + to[0], r0*f1.x + m0*so[1] + to[1],
                    r0*f2.x + m0*so[2] + to[2], r0*f3.x + m0*so[3] + to[3]);
        *(uint2*)&b_Q[side][bh][w0+p+1][ty*4] =
            pack4bf(r1*f0.y + m1*so[0] + to[0], r1*f1.y + m1*so[1] + to[1],
                    r1*f2.y + m1*so[2] + to[2], r1*f3.y + m1*so[3] + to[3]);
    }

    #pragma unroll
    for (int i = 0; i < 4; i++)
        #pragma unroll
        for (int j = 0; j < 6; j++) acc2[i][j] = 0ULL;
    for (int c = 0; c < Cc; c++) {
        float4 wv = make_float4(w2[(ty*4+0)*Cc+c], w2[(ty*4+1)*Cc+c],
                                w2[(ty*4+2)*Cc+c], w2[(ty*4+3)*Cc+c]);
        u64 A0 = dup2f(wv.x), A1 = dup2f(wv.y), A2 = dup2f(wv.z), A3 = dup2f(wv.w);
        #pragma unroll
        for (int j = 0; j < 6; j++) {
            u64 X = *(const u64*)&xs[c*PIX + 2*tx + 32*j];
            fma2(acc2[0][j], A0, X); fma2(acc2[1][j], A1, X);
            fma2(acc2[2][j], A2, X); fma2(acc2[3][j], A3, X);
        }
    }
    float bo[4] = {b2[ty*4], b2[ty*4+1], b2[ty*4+2], b2[ty*4+3]};
    #pragma unroll
    for (int j = 0; j < 6; j++) {
        int p = 2*tx + 32*j;
        #pragma unroll
        for (int i = 0; i < 4; i++) {
            float2 f = up2(acc2[i][j]);
            __nv_bfloat162 pr = __floats2bfloat162_rn(f.x + bo[i], f.y + bo[i]);
            *(__nv_bfloat162*)&b_VT[side][bh][ty*4+i][w0+p] = pr;
        }
    }
}

// ================= MMA helpers =================
#define APAD 40
#define APAD2 72
__device__ __forceinline__ void ldsm4(u32& r0, u32& r1, u32& r2, u32& r3, u32 addr) {
    asm volatile("ldmatrix.sync.aligned.m8n8.x4.shared.b16 {%0,%1,%2,%3}, [%4];"
                 : "=r"(r0), "=r"(r1), "=r"(r2), "=r"(r3) : "r"(addr));
}
__device__ __forceinline__ void mma_bf16(float* c, const u32* a, u32 b0, u32 b1) {
    asm volatile("mma.sync.aligned.m16n8k16.row.col.f32.bf16.bf16.f32 "
                 "{%0,%1,%2,%3}, {%4,%5,%6,%7}, {%8,%9}, {%0,%1,%2,%3};"
                 : "+f"(c[0]), "+f"(c[1]), "+f"(c[2]), "+f"(c[3])
                 : "r"(a[0]), "r"(a[1]), "r"(a[2]), "r"(a[3]), "r"(b0), "r"(b1));
}

// ================= K2: attention logits via warp MMA -> bf16 A =================
__global__ void __launch_bounds__(256) k2_attn_mma()
{
    __shared__ __align__(16) __nv_bfloat16 As[128][APAD];
    __shared__ __align__(16) __nv_bfloat16 Bs[128][APAD];
    const int bh = blockIdx.z;
    const int v0 = blockIdx.x * 128, w0 = blockIdx.y * 128;
    const int tid = threadIdx.x, wid = tid >> 5, lane = tid & 31;
    const int wm = wid >> 2, wn = wid & 3;
    const __nv_bfloat16* __restrict__ Ag = &b_Q[0][bh][w0][0];
    const __nv_bfloat16* __restrict__ Bg = &b_Q[1][bh][v0][0];

    float c[4][4][4];
    #pragma unroll
    for (int mt = 0; mt < 4; mt++)
        #pragma unroll
        for (int nt = 0; nt < 4; nt++)
            #pragma unroll
            for (int i = 0; i < 4; i++) c[mt][nt][i] = 0.f;

    const u32 a_base = smem_u32(As), b_base = smem_u32(Bs);
    const u32 a_row = wm*64 + (lane & 15);
    const u32 a_coff = (lane >> 4) * 16;
    const u32 b_row = wn*32 + (lane & 7) + ((lane >> 4) << 3);
    const u32 b_coff = ((lane >> 3) & 1) * 16;

    for (int ch = 0; ch < 2; ch++) {
        #pragma unroll
        for (int p = 0; p < 2; p++) {
            int idx = tid + p*256;
            int row = idx >> 2, seg = idx & 3;
            const int go = row*Cc + ch*32 + seg*8;
            uint4 va = *(const uint4*)(Ag + go);
            uint4 vb = *(const uint4*)(Bg + go);
            *(uint2*)&As[row][seg*8]     = make_uint2(va.x, va.y);
            *(uint2*)&As[row][seg*8 + 4] = make_uint2(va.z, va.w);
            *(uint2*)&Bs[row][seg*8]     = make_uint2(vb.x, vb.y);
            *(uint2*)&Bs[row][seg*8 + 4] = make_uint2(vb.z, vb.w);
        }
        __syncthreads();
        #pragma unroll
        for (int ks = 0; ks < 2; ks++) {
            const u32 kb = ks*32;
            u32 bf[2][4];
            #pragma unroll
            for (int hgrp = 0; hgrp < 2; hgrp++) {
                u32 addr = b_base + (b_row + hgrp*16)*(APAD*2) + kb + b_coff;
                ldsm4(bf[hgrp][0], bf[hgrp][1], bf[hgrp][2], bf[hgrp][3], addr);
            }
            #pragma unroll
            for (int mt = 0; mt < 4; mt++) {
                u32 a[4];
                u32 addr = a_base + (a_row + mt*16)*(APAD*2) + kb + a_coff;
                ldsm4(a[0], a[1], a[2], a[3], addr);
                #pragma unroll
                for (int nt = 0; nt < 4; nt++)
                    mma_bf16(c[mt][nt], a, bf[nt >> 1][(nt & 1)*2], bf[nt >> 1][(nt & 1)*2 + 1]);
            }
        }
        __syncthreads();
    }

    const float s = 0.125f;
    #pragma unroll
    for (int mt = 0; mt < 4; mt++) {
        #pragma unroll
        for (int hh = 0; hh < 2; hh++) {
            int w = w0 + wm*64 + mt*16 + (lane >> 2) + hh*8;
            #pragma unroll
            for (int nt = 0; nt < 4; nt++) {
                int v = v0 + wn*32 + nt*8 + (lane & 3)*2;
                __nv_bfloat162 o = __floats2bfloat162_rn(c[mt][nt][hh*2]*s, c[mt][nt][hh*2+1]*s);
                *(__nv_bfloat162*)&b_A[bh][w][v] = o;
            }
        }
    }
}

// ================= K3a: row stats =================
__global__ void k3a_rowstats()
{
    const int bh = blockIdx.y;
    const int w = blockIdx.x*8 + (threadIdx.x >> 5);
    const int lane = threadIdx.x & 31;
    const __nv_bfloat16* __restrict__ row = b_A[bh][w];
    float f[3][4];
    #pragma unroll
    for (int t = 0; t < 3; t++)
        unp4(*(const uint2*)(row + lane*4 + t*128), f[t]);
    float m = -1e30f;
    #pragma unroll
    for (int t = 0; t < 3; t++)
        #pragma unroll
        for (int e = 0; e < 4; e++) m = fmaxf(m, f[t][e]);
    #pragma unroll
    for (int o = 16; o; o >>= 1) m = fmaxf(m, __shfl_xor_sync(0xffffffffu, m, o));
    float s = 0.f;
    #pragma unroll
    for (int t = 0; t < 3; t++)
        #pragma unroll
        for (int e = 0; e < 4; e++) s += __expf(f[t][e] - m);
    #pragma unroll
    for (int o = 16; o; o >>= 1) s += __shfl_xor_sync(0xffffffffu, s, o);
    if (!lane) { g_rmax[bh][w] = m; g_rinv[bh][w] = 1.f/s; }
}

// ================= K3b: col stats + ms_r2l =================
__global__ void __launch_bounds__(256) k3b_colstats()
{
    __shared__ float sRm[Ww], sRi[Ww];
    __shared__ float red[3][16][16];
    const int bh = blockIdx.y;
    const int tid = threadIdx.x;
    const int lane = tid & 15, grp = tid >> 4;
    const int v = blockIdx.x*16 + lane;

    for (int i = tid; i < Ww; i += 256) { sRm[i] = g_rmax[bh][i]; sRi[i] = g_rinv[bh][i]; }

    float a[24];
    #pragma unroll
    for (int t = 0; t < 24; t++) a[t] = __bfloat162float(b_A[bh][grp + 16*t][v]);
    __syncthreads();

    float m = -1e30f;
    #pragma unroll
    for (int t = 0; t < 24; t++) m = fmaxf(m, a[t]);
    red[0][grp][lane] = m;
    __syncthreads();
    if (grp == 0) {
        for (int k = 1; k < 16; k++) m = fmaxf(m, red[0][k][lane]);
        red[0][0][lane] = m;
    }
    __syncthreads();
    m = red[0][0][lane];

    float s = 0.f, ms = 0.f;
    #pragma unroll
    for (int t = 0; t < 24; t++) {
        int row = grp + 16*t;
        s  += __expf(a[t] - m);
        ms += __expf(a[t] - sRm[row]) * sRi[row];
    }
    red[1][grp][lane] = s; red[2][grp][lane] = ms;
    __syncthreads();
    if (grp == 0) {
        for (int k = 1; k < 16; k++) { s += red[1][k][lane]; ms += red[2][k][lane]; }
        g_cmax[bh][v] = m;
        g_cinv[bh][v] = 1.f/s;
        g_ms_r2l[bh][v] = ms;
    }
}

// ================= K4: bf16 M matrices in both orientations =================
__global__ void __launch_bounds__(256) k4_writeM()
{
    __shared__ __align__(16) __nv_bfloat16 s1[64][68];
    __shared__ __align__(16) __nv_bfloat16 s2[64][68];
    const int bh = blockIdx.y;
    const int u0 = blockIdx.x*64;
    const int tid = threadIdx.x;
    const int row = tid >> 2, seg = tid & 3;
    const int u = u0 + row;
    const float rm = g_rmax[bh][u], ri = g_rinv[bh][u];
    float msum = 0.f;

    for (int ct = 0; ct < 6; ct++) {
        const int c0 = ct*64 + seg*16;
        #pragma unroll
        for (int q = 0; q < 4; q++) {
            int v = c0 + q*4;
            float a[4];
            unp4(*(const uint2*)&b_A[bh][u][v], a);
            float4 cm = *(const float4*)&g_cmax[bh][v];
            float4 ci = *(const float4*)&g_cinv[bh][v];
            float4 m1 = make_float4(__expf(a[0]-rm)*ri, __expf(a[1]-rm)*ri,
                                    __expf(a[2]-rm)*ri, __expf(a[3]-rm)*ri);
            float4 m2 = make_float4(__expf(a[0]-cm.x)*ci.x, __expf(a[1]-cm.y)*ci.y,
                                    __expf(a[2]-cm.z)*ci.z, __expf(a[3]-cm.w)*ci.w);
            uint2 p1 = pack4bf(m1.x, m1.y, m1.z, m1.w);
            uint2 p2 = pack4bf(m2.x, m2.y, m2.z, m2.w);
            *(uint2*)&b_Mr2l[bh][u][v] = p1;
            *(uint2*)&b_MLT[bh][u][v]  = p2;
            *(uint2*)&s1[row][seg*16 + q*4] = p1;
            *(uint2*)&s2[row][seg*16 + q*4] = p2;
            msum += m2.x + m2.y + m2.z + m2.w;
        }
        __syncthreads();
        {
            const int vl = row;
            const u16* p1r = (const u16*)s1;
            const u16* p2r = (const u16*)s2;
            #pragma unroll
            for (int q = 0; q < 4; q++) {
                int ub = seg*16 + q*4;
                uint2 o1, o2;
                o1.x = (u32)p1r[(ub+0)*68 + vl] | ((u32)p1r[(ub+1)*68 + vl] << 16);
                o1.y = (u32)p1r[(ub+2)*68 + vl] | ((u32)p1r[(ub+3)*68 + vl] << 16);
                o2.x = (u32)p2r[(ub+0)*68 + vl] | ((u32)p2r[(ub+1)*68 + vl] << 16);
                o2.y = (u32)p2r[(ub+2)*68 + vl] | ((u32)p2r[(ub+3)*68 + vl] << 16);
                *(uint2*)&b_Mr2lT[bh][ct*64 + vl][u0 + ub] = o1;
                *(uint2*)&b_MLTT[bh][ct*64 + vl][u0 + ub]  = o2;
            }
        }
        __syncthreads();
    }
    msum += __shfl_xor_sync(0xffffffffu, msum, 1);
    msum += __shfl_xor_sync(0xffffffffu, msum, 2);
    if (seg == 0) g_ms_l2r[bh][u] = msum;
}

// ================= K5: cycle loss, double-buffered warp MMA, k-chunk 64 =================
__global__ void __launch_bounds__(256) k5_cycle_mma()
{
    extern __shared__ __nv_bfloat16 dyn[];
    __shared__ float red[256];
    const int z = blockIdx.z, term = z & 1, bh = z >> 1;
    const int u0 = blockIdx.x*128, w0 = blockIdx.y*128;
    const int tid = threadIdx.x, wid = tid >> 5, lane = tid & 31;
    const int wm = wid >> 2, wn = wid & 3;
    const __nv_bfloat16* __restrict__ Ag = term == 0 ? &b_Mr2l[bh][w0][0] : &b_MLTT[bh][w0][0];
    const __nv_bfloat16* __restrict__ Bg = term == 0 ? &b_MLT[bh][u0][0]  : &b_Mr2lT[bh][u0][0];

    const int BUF = 128*APAD2;
    __nv_bfloat16* A0 = dyn;
    __nv_bfloat16* B0 = dyn + BUF;
    __nv_bfloat16* A1 = dyn + 2*BUF;
    __nv_bfloat16* B1 = dyn + 3*BUF;

    float c[4][4][4];
    #pragma unroll
    for (int mt = 0; mt < 4; mt++)
        #pragma unroll
        for (int nt = 0; nt < 4; nt++)
            #pragma unroll
            for (int i = 0; i < 4; i++) c[mt][nt][i] = 0.f;

    const u32 abase[2] = {smem_u32(A0), smem_u32(A1)};
    const u32 bbase[2] = {smem_u32(B0), smem_u32(B1)};
    const u32 a_row = wm*64 + (lane & 15);
    const u32 a_coff = (lane >> 4) * 16;
    const u32 b_row = wn*32 + (lane & 7) + ((lane >> 4) << 3);
    const u32 b_coff = ((lane >> 3) & 1) * 16;

    // loader geometry: p=0..3, idx=tid+p*256, row=idx>>3 (0..127), seg=idx&7 (0..7)
    int lrow[4], lseg[4];
    #pragma unroll
    for (int p = 0; p < 4; p++) { int idx = tid + p*256; lrow[p] = idx >> 3; lseg[p] = idx & 7; }

    // preload chunk 0 into buffer 0
    #pragma unroll
    for (int p = 0; p < 4; p++) {
        const long go = (long)lrow[p]*Ww + lseg[p]*8;
        uint4 va = *(const uint4*)(Ag + go);
        uint4 vb = *(const uint4*)(Bg + go);
        __nv_bfloat16* Ad = A0 + lrow[p]*APAD2 + lseg[p]*8;
        __nv_bfloat16* Bd = B0 + lrow[p]*APAD2 + lseg[p]*8;
        *(uint2*)Ad       = make_uint2(va.x, va.y);
        *(uint2*)(Ad + 4) = make_uint2(va.z, va.w);
        *(uint2*)Bd       = make_uint2(vb.x, vb.y);
        *(uint2*)(Bd + 4) = make_uint2(vb.z, vb.w);
    }
    __syncthreads();

    for (int ch = 0; ch < 6; ch++) {
        const int cur = ch & 1, nxt = cur ^ 1;
        uint4 pva[4], pvb[4];
        if (ch < 5) {
            #pragma unroll
            for (int p = 0; p < 4; p++) {
                const long go = (long)lrow[p]*Ww + (ch+1)*64 + lseg[p]*8;
                pva[p] = *(const uint4*)(Ag + go);
                pvb[p] = *(const uint4*)(Bg + go);
            }
        }
        #pragma unroll
        for (int ks = 0; ks < 4; ks++) {
            const u32 kb = ks*32;
            u32 bf[2][4];
            #pragma unroll
            for (int hgrp = 0; hgrp < 2; hgrp++) {
                u32 addr = bbase[cur] + (b_row + hgrp*16)*(APAD2*2) + kb + b_coff;
                ldsm4(bf[hgrp][0], bf[hgrp][1], bf[hgrp][2], bf[hgrp][3], addr);
            }
            #pragma unroll
            for (int mt = 0; mt < 4; mt++) {
                u32 a[4];
                u32 addr = abase[cur] + (a_row + mt*16)*(APAD2*2) + kb + a_coff;
                ldsm4(a[0], a[1], a[2], a[3], addr);
                #pragma unroll
                for (int nt = 0; nt < 4; nt++)
                    mma_bf16(c[mt][nt], a, bf[nt >> 1][(nt & 1)*2], bf[nt >> 1][(nt & 1)*2 + 1]);
            }
        }
        if (ch < 5) {
            __nv_bfloat16* An = nxt ? A1 : A0;
            __nv_bfloat16* Bn = nxt ? B1 : B0;
            #pragma unroll
            for (int p = 0; p < 4; p++) {
                __nv_bfloat16* Ad = An + lrow[p]*APAD2 + lseg[p]*8;
                __nv_bfloat16* Bd = Bn + lrow[p]*APAD2 + lseg[p]*8;
                *(uint2*)Ad       = make_uint2(pva[p].x, pva[p].y);
                *(uint2*)(Ad + 4) = make_uint2(pva[p].z, pva[p].w);
                *(uint2*)Bd       = make_uint2(pvb[p].x, pvb[p].y);
                *(uint2*)(Bd + 4) = make_uint2(pvb[p].z, pvb[p].w);
            }
        }
        __syncthreads();
    }

    const float* __restrict__ msrow = (term == 0) ? g_ms_l2r[bh] : g_ms_r2l[bh];
    float lsum = 0.f;
    #pragma unroll
    for (int nt = 0; nt < 4; nt++) {
        #pragma unroll
        for (int jj = 0; jj < 2; jj++) {
            int u = u0 + wn*32 + nt*8 + (lane & 3)*2 + jj;
            float mk = (msrow[u] > 0.1f) ? 1.f : 0.f;
            #pragma unroll
            for (int mt = 0; mt < 4; mt++) {
                #pragma unroll
                for (int hh = 0; hh < 2; hh++) {
                    int w = w0 + wm*64 + mt*16 + (lane >> 2) + hh*8;
                    float dv = c[mt][nt][hh*2 + jj];
                    lsum += mk * fabsf(dv - ((w == u) ? 1.f : 0.f));
                }
            }
        }
    }
    red[tid] = lsum; __syncthreads();
    for (int s = 128; s; s >>= 1) { if (tid < s) red[tid] += red[tid+s]; __syncthreads(); }
    if (!tid) g_p_cyc[z*9 + blockIdx.y*3 + blockIdx.x] = red[0];
}

// ================= K6: outputs via warp MMA, both sides in one launch =================
__global__ void __launch_bounds__(256) k6_mma(const float* __restrict__ x_l,
                                              const float* __restrict__ x_r,
                                              const float* __restrict__ beta,
                                              const float* __restrict__ gamma,
                                              float* __restrict__ out_xl,
                                              float* __restrict__ out_xr)
{
    __shared__ __align__(16) __nv_bfloat16 As[128][APAD];
    __shared__ __align__(16) __nv_bfloat16 Bs[64][APAD];
    const int side = blockIdx.z;
    const float* __restrict__ x  = side ? x_r : x_l;
    const float* __restrict__ bg = side ? gamma : beta;
    float* __restrict__ out = side ? out_xr : out_xl;
    const int bh = blockIdx.y;
    const int b = bh / Hh, h = bh % Hh;
    const int w0 = blockIdx.x * 128;
    const int tid = threadIdx.x, wid = tid >> 5, lane = tid & 31;
    const int wm = wid >> 2, wn = wid & 3;
    const __nv_bfloat16* __restrict__ Ag = side == 0 ? &b_Mr2l[bh][w0][0] : &b_MLTT[bh][w0][0];
    const __nv_bfloat16* __restrict__ Bg = &b_VT[side == 0 ? 1 : 0][bh][0][0];

    float c[4][2][4];
    #pragma unroll
    for (int mt = 0; mt < 4; mt++)
        #pragma unroll
        for (int nt = 0; nt < 2; nt++)
            #pragma unroll
            for (int i = 0; i < 4; i++) c[mt][nt][i] = 0.f;

    const u32 a_base = smem_u32(As), b_base = smem_u32(Bs);
    const u32 a_row = wm*64 + (lane & 15);
    const u32 a_coff = (lane >> 4) * 16;
    const u32 b_row = wn*16 + (lane & 7) + ((lane >> 4) << 3);
    const u32 b_coff = ((lane >> 3) & 1) * 16;

    for (int ch = 0; ch < 12; ch++) {
        #pragma unroll
        for (int p = 0; p < 2; p++) {
            int idx = tid + p*256;
            int row = idx >> 2, seg = idx & 3;
            uint4 va = *(const uint4*)(Ag + (long)row*Ww + ch*32 + seg*8);
            *(uint2*)&As[row][seg*8]     = make_uint2(va.x, va.y);
            *(uint2*)&As[row][seg*8 + 4] = make_uint2(va.z, va.w);
        }
        {
            int row = tid >> 2, seg = tid & 3;
            uint4 vb = *(const uint4*)(Bg + (long)row*Ww + ch*32 + seg*8);
            *(uint2*)&Bs[row][seg*8]     = make_uint2(vb.x, vb.y);
            *(uint2*)&Bs[row][seg*8 + 4] = make_uint2(vb.z, vb.w);
        }
        __syncthreads();
        #pragma unroll
        for (int ks = 0; ks < 2; ks++) {
            const u32 kb = ks*32;
            u32 bfr[4];
            ldsm4(bfr[0], bfr[1], bfr[2], bfr[3], b_base + b_row*(APAD*2) + kb + b_coff);
            #pragma unroll
            for (int mt = 0; mt < 4; mt++) {
                u32 a[4];
                ldsm4(a[0], a[1], a[2], a[3], a_base + (a_row + mt*16)*(APAD*2) + kb + a_coff);
                mma_bf16(c[mt][0], a, bfr[0], bfr[1]);
                mma_bf16(c[mt][1], a, bfr[2], bfr[3]);
            }
        }
        __syncthreads();
    }

    #pragma unroll
    for (int nt = 0; nt < 2; nt++) {
        #pragma unroll
        for (int jj = 0; jj < 2; jj++) {
            int cc = wn*16 + nt*8 + (lane & 3)*2 + jj;
            float bgc = bg[cc];
            #pragma unroll
            for (int mt = 0; mt < 4; mt++) {
                #pragma unroll
                for (int hh = 0; hh < 2; hh++) {
                    int w = w0 + wm*64 + mt*16 + (lane >> 2) + hh*8;
                    long gi = (((long)b*Cc + cc)*Hh + h)*Ww + w;
                    out[gi] = x[gi] + bgc * c[mt][nt][hh*2 + jj];
                }
            }
        }
    }
}

// ================= K7a: photo term 1 =================
__global__ void k7a_photo1(const float* __restrict__ LRl, const float* __restrict__ LRr)
{
    __shared__ float lr[3][Ww];
    __shared__ float r8[8];
    const int bh = blockIdx.y;
    const int b = bh / Hh, h = bh % Hh;
    const int w = blockIdx.x*8 + (threadIdx.x >> 5);
    const int lane = threadIdx.x & 31;
    for (int idx = threadIdx.x; idx < 3*Ww; idx += 256) {
        int ch = idx / Ww, v = idx % Ww;
        lr[ch][v] = LRr[(((long)b*3 + ch)*Hh + h)*Ww + v];
    }
    __syncthreads();
    float a0 = 0.f, a1 = 0.f, a2 = 0.f;
    const __nv_bfloat16* __restrict__ mrow = b_Mr2l[bh][w];
    #pragma unroll
    for (int t = 0; t < 3; t++) {
        int v4 = lane*4 + t*128;
        uint2 pk = *(const uint2*)(mrow + v4);
        float f[4]; unp4(pk, f);
        #pragma unroll
        for (int e = 0; e < 4; e++) {
            a0 += f[e]*lr[0][v4+e]; a1 += f[e]*lr[1][v4+e]; a2 += f[e]*lr[2][v4+e];
        }
    }
    #pragma unroll
    for (int o = 16; o; o >>= 1) {
        a0 += __shfl_xor_sync(0xffffffffu, a0, o);
        a1 += __shfl_xor_sync(0xffffffffu, a1, o);
        a2 += __shfl_xor_sync(0xffffffffu, a2, o);
    }
    if (!lane) {
        float mk = (g_ms_l2r[bh][w] > 0.1f) ? 1.f : 0.f;
        long base = (((long)b*3)*Hh + h)*Ww + w;
        float part = mk * (fabsf(LRl[base] - a0)
                         + fabsf(LRl[base + (long)Hh*Ww] - a1)
                         + fabsf(LRl[base + 2L*Hh*Ww] - a2));
        r8[threadIdx.x >> 5] = part;
    }
    __syncthreads();
    if (threadIdx.x == 0) {
        float s = 0.f;
        for (int k = 0; k < 8; k++) s += r8[k];
        g_p_ph1[bh*48 + blockIdx.x] = s;
    }
}

// ================= K7b: photo term 2 =================
__global__ void k7b_photo2(const float* __restrict__ LRl, const float* __restrict__ LRr)
{
    __shared__ float la[3][Ww], lb[3][Ww];
    __shared__ float red[128];
    const int bh = blockIdx.x;
    const int b = bh / Hh, h = bh % Hh;
    const int tid = threadIdx.x;
    for (int idx = tid; idx < 3*Ww; idx += 128) {
        int ch = idx / Ww, w = idx % Ww;
        long gi = (((long)b*3 + ch)*Hh + h)*Ww + w;
        la[ch][w] = LRl[gi];
        lb[ch][w] = LRr[gi];
    }
    __syncthreads();
    float acc[3][3] = {};
    for (int v = 0; v < Ww; v++) {
        const __nv_bfloat16* __restrict__ mr = b_MLT[bh][v];
        float l0 = la[0][v], l1 = la[1][v], l2 = la[2][v];
        #pragma unroll
        for (int s = 0; s < 3; s++) {
            float m = __bfloat162float(mr[tid + s*128]);
            acc[s][0] += m*l0; acc[s][1] += m*l1; acc[s][2] += m*l2;
        }
    }
    float part = 0.f;
    #pragma unroll
    for (int s = 0; s < 3; s++) {
        int w = tid + s*128;
        float mk = (g_ms_r2l[bh][w] > 0.1f) ? 1.f : 0.f;
        part += mk * (fabsf(lb[0][w] - acc[s][0])
                    + fabsf(lb[1][w] - acc[s][1])
                    + fabsf(lb[2][w] - acc[s][2]));
    }
    red[tid] = part; __syncthreads();
    for (int s = 64; s; s >>= 1) { if (tid < s) red[tid] += red[tid+s]; __syncthreads(); }
    if (!tid) g_p_ph2[bh] = red[0];
}

// ================= K8: smoothness =================
__global__ void k8_smooth()
{
    __shared__ float redh[256], redw[256];
    const int mat = blockIdx.z, bh = blockIdx.y, w0 = blockIdx.x*16;
    const int h = bh % Hh;
    const __nv_bfloat16* __restrict__ M = mat ? &b_MLT[0][0][0] : &b_Mr2l[0][0][0];
    const int tid = threadIdx.x;
    const bool hok = (h < Hh - 1);
    float sh = 0.f, sw = 0.f;
    for (int i = tid; i < 16*96; i += 256) {
        int w = w0 + i/96, v4 = (i%96)*4;
        long base = ((long)bh*Ww + w)*Ww + v4;
        float cv[4]; unp4(*(const uint2*)(M + base), cv);
        if (hok) {
            float nh[4]; unp4(*(const uint2*)(M + base + (long)Ww*Ww), nh);
            sh += fabsf(cv[0]-nh[0]) + fabsf(cv[1]-nh[1])
                + fabsf(cv[2]-nh[2]) + fabsf(cv[3]-nh[3]);
        }
        if (w < Ww - 1) {
            float nr[4]; unp4(*(const uint2*)(M + base + Ww), nr);
            sw += fabsf(cv[0]-nr[1]) + fabsf(cv[1]-nr[2]) + fabsf(cv[2]-nr[3]);
            if (v4 < 380) {
                float n4 = __bfloat162float(M[base + Ww + 4]);
                sw += fabsf(cv[3] - n4);
            }
        }
    }
    redh[tid] = sh; redw[tid] = sw; __syncthreads();
    for (int s = 128; s; s >>= 1) {
        if (tid < s) { redh[tid] += redh[tid+s]; redw[tid] += redw[tid+s]; }
        __syncthreads();
    }
    if (!tid) {
        int slot = (mat*BHn + bh)*24 + blockIdx.x;
        g_p_smh[slot] = redh[0];
        g_p_smw[slot] = redw[0];
    }
}

// ================= K9 =================
__global__ void k9_final(const float* __restrict__ loss_in, float* __restrict__ out_loss)
{
    __shared__ double red[256];
    const int tid = threadIdx.x;
    double acc[4] = {0.0, 0.0, 0.0, 0.0};
    for (int i = tid; i < NP_CYC; i += 256) acc[0] += (double)g_p_cyc[i];
    for (int i = tid; i < NP_PH1; i += 256) acc[1] += (double)g_p_ph1[i];
    for (int i = tid; i < NP_PH2; i += 256) acc[1] += (double)g_p_ph2[i];
    for (int i = tid; i < NP_SM;  i += 256) acc[2] += (double)g_p_smh[i];
    for (int i = tid; i < NP_SM;  i += 256) acc[3] += (double)g_p_smw[i];
    double tot[4];
    for (int a = 0; a < 4; a++) {
        red[tid] = acc[a]; __syncthreads();
        for (int s = 128; s; s >>= 1) { if (tid < s) red[tid] += red[tid+s]; __syncthreads(); }
        tot[a] = red[0]; __syncthreads();
    }
    if (!tid) {
        double lc = tot[0] / ((double)Bz*Hh*Ww*Ww);
        double lp = tot[1] / ((double)Bz*3*Hh*Ww);
        double lh = tot[2] / ((double)Bz*(Hh-1)*Ww*Ww);
        double lw = tot[3] / ((double)Bz*Hh*(Ww-1)*(Ww-1));
        out_loss[0] = (float)((double)loss_in[0] + 0.0025*(lp + 0.1*(lw + lh) + lc));
    }
}

extern "C" void kernel_launch(void* const* d_in, const int* in_sizes, int n_in,
                              void* d_out, int out_size)
{
    (void)in_sizes; (void)n_in; (void)out_size;
    const float* x_l   = (const float*)d_in[0];
    const float* x_r   = (const float*)d_in[1];
    const float* LRl   = (const float*)d_in[2];
    const float* LRr   = (const float*)d_in[3];
    const float* lossi = (const float*)d_in[4];
    const float* nlw = (const float*)d_in[5];
    const float* nlb = (const float*)d_in[6];
    const float* nrw = (const float*)d_in[7];
    const float* nrb = (const float*)d_in[8];
    const float* lp1w = (const float*)d_in[9];
    const float* lp1b = (const float*)d_in[10];
    const float* rp1w = (const float*)d_in[11];
    const float* rp1b = (const float*)d_in[12];
    const float* lp2w = (const float*)d_in[13];
    const float* lp2b = (const float*)d_in[14];
    const float* rp2w = (const float*)d_in[15];
    const float* rp2b = (const float*)d_in[16];
    const float* beta  = (const float*)d_in[17];
    const float* gamma = (const float*)d_in[18];

    float* out = (float*)d_out;
    float* out_xl   = out;
    float* out_xr   = out + NX;
    float* out_lrl  = out + 2L*NX;
    float* out_lrr  = out + 2L*NX + NLR;
    float* out_loss = out + 2L*NX + 2L*NLR;

    const size_t smem1 = (size_t)(Cc*PIX + 2*Cc*Cc + 2*Cc + 2*PIX) * sizeof(float);
    cudaFuncSetAttribute(k1_lnproj, cudaFuncAttributeMaxDynamicSharedMemorySize, (int)smem1);
    const int smem5 = 4 * 128 * APAD2 * (int)sizeof(__nv_bfloat16);
    cudaFuncSetAttribute(k5_cycle_mma, cudaFuncAttributeMaxDynamicSharedMemorySize, smem5);

    k1_lnproj<<<dim3(2, BHn, 2), 256, smem1>>>(x_l, x_r, nlw, nlb, nrw, nrb,
                                               lp1w, lp1b, rp1w, rp1b,
                                               lp2w, lp2b, rp2w, rp2b);
    k2_attn_mma<<<dim3(3, 3, BHn), 256>>>();
    k3a_rowstats<<<dim3(48, BHn), 256>>>();
    k3b_colstats<<<dim3(24, BHn), 256>>>();
    k4_writeM<<<dim3(6, BHn), 256>>>();
    k5_cycle_mma<<<dim3(3, 3, BHn*2), 256, smem5>>>();
    k6_mma<<<dim3(3, BHn, 2), 256>>>(x_l, x_r, beta, gamma, out_xl, out_xr);
    k7a_photo1<<<dim3(48, BHn), 256>>>(LRl, LRr);
    k7b_photo2<<<BHn, 128>>>(LRl, LRr);
    k8_smooth<<<dim3(24, BHn, 2), 256>>>();
    cudaMemcpyAsync(out_lrl, LRl, (size_t)NLR*sizeof(float), cudaMemcpyDeviceToDevice, 0);
    cudaMemcpyAsync(out_lrr, LRr, (size_t)NLR*sizeof(float), cudaMemcpyDeviceToDevice, 0);
    k9_final<<<1, 256>>>(lossi, out_loss);
}

// round 17
// speedup vs baseline: 1.1629x; 1.1629x over previous
#include <cuda_runtime.h>
#include <cuda_bf16.h>
#include <math.h>

#define Bz 4
#define Cc 64
#define Hh 96
#define Ww 384
#define BHn (Bz*Hh)
#define NX (Bz*Cc*Hh*Ww)
#define NLR (Bz*3*Hh*Ww)
#define EPS 1e-6f

typedef unsigned long long u64;
typedef unsigned int u32;
typedef unsigned short u16;
__device__ __forceinline__ u64 dup2f(float x) {
    u64 r; asm("mov.b64 %0, {%1, %1};" : "=l"(r) : "f"(x)); return r;
}
__device__ __forceinline__ void fma2(u64 &d, u64 a, u64 b) {
    asm("fma.rn.f32x2 %0, %1, %2, %0;" : "+l"(d) : "l"(a), "l"(b));
}
__device__ __forceinline__ float2 up2(u64 v) {
    float2 r; asm("mov.b64 {%0, %1}, %2;" : "=f"(r.x), "=f"(r.y) : "l"(v)); return r;
}
__device__ __forceinline__ u32 smem_u32(const void* p) {
    u32 a; asm("{ .reg .u64 t; cvta.to.shared.u64 t, %1; cvt.u32.u64 %0, t; }" : "=r"(a) : "l"(p));
    return a;
}
__device__ __forceinline__ void unp4(uint2 p, float* f) {
    __nv_bfloat162 a = *(__nv_bfloat162*)&p.x;
    __nv_bfloat162 b = *(__nv_bfloat162*)&p.y;
    f[0] = __bfloat162float(a.x); f[1] = __bfloat162float(a.y);
    f[2] = __bfloat162float(b.x); f[3] = __bfloat162float(b.y);
}
__device__ __forceinline__ uint2 pack4bf(float a, float b, float c, float d) {
    __nv_bfloat162 p0 = __floats2bfloat162_rn(a, b);
    __nv_bfloat162 p1 = __floats2bfloat162_rn(c, d);
    uint2 r;
    r.x = *(u32*)&p0; r.y = *(u32*)&p1;
    return r;
}

__device__ __align__(16) __nv_bfloat16 b_Q[2][BHn][Ww][Cc];
__device__ __align__(16) __nv_bfloat16 b_A[BHn][Ww][Ww];
__device__ __align__(16) __nv_bfloat16 b_Mr2l[BHn][Ww][Ww];
__device__ __align__(16) __nv_bfloat16 b_MLT[BHn][Ww][Ww];
__device__ __align__(16) __nv_bfloat16 b_Mr2lT[BHn][Ww][Ww];
__device__ __align__(16) __nv_bfloat16 b_MLTT[BHn][Ww][Ww];
__device__ __align__(16) __nv_bfloat16 b_VT[2][BHn][Cc][Ww];
__device__ __align__(16) float g_rmax[BHn][Ww];
__device__ __align__(16) float g_rinv[BHn][Ww];
__device__ __align__(16) float g_cmax[BHn][Ww];
__device__ __align__(16) float g_cinv[BHn][Ww];
__device__ __align__(16) float g_ms_r2l[BHn][Ww];
__device__ __align__(16) float g_ms_l2r[BHn][Ww];

#define NP_CYC (2*BHn*9)
#define NP_PH1 (48*BHn)
#define NP_PH2 (BHn)
#define NP_SM  (2*BHn*24)
__device__ float g_p_cyc[NP_CYC];
__device__ float g_p_ph1[NP_PH1];
__device__ float g_p_ph2[NP_PH2];
__device__ float g_p_smh[NP_SM];
__device__ float g_p_smw[NP_SM];

// ====== K1: LN + both 1x1 projections, FFMA2, both sides in one launch ======
#define PIX 192
__global__ void k1_lnproj(const float* __restrict__ x_l, const float* __restrict__ x_r,
                          const float* __restrict__ nlw, const float* __restrict__ nlb,
                          const float* __restrict__ nrw, const float* __restrict__ nrb,
                          const float* __restrict__ lp1w, const float* __restrict__ lp1b,
                          const float* __restrict__ rp1w, const float* __restrict__ rp1b,
                          const float* __restrict__ lp2w, const float* __restrict__ lp2b,
                          const float* __restrict__ rp2w, const float* __restrict__ rp2b)
{
    extern __shared__ float sm[];
    float* xs   = sm;
    float* w1   = xs + Cc*PIX;
    float* w2   = w1 + Cc*Cc;
    float* s1   = w2 + Cc*Cc;
    float* t1   = s1 + Cc;
    float* mval = t1 + Cc;
    float* rval = mval + PIX;

    const int side = blockIdx.z;
    const float* __restrict__ x  = side ? x_r : x_l;
    const float* __restrict__ nw = side ? nrw : nlw;
    const float* __restrict__ nb = side ? nrb : nlb;
    const float* __restrict__ p1 = side ? rp1w : lp1w;
    const float* __restrict__ b1 = side ? rp1b : lp1b;
    const float* __restrict__ p2 = side ? rp2w : lp2w;
    const float* __restrict__ b2 = side ? rp2b : lp2b;

    const int bh = blockIdx.y;
    const int b = bh / Hh, h = bh % Hh;
    const int w0 = blockIdx.x * PIX;
    const int tid = threadIdx.x;

    for (int idx = tid; idx < Cc*Cc; idx += 256) {
        int c = idx & 63;
        w1[idx] = p1[idx] * nw[c];
        w2[idx] = p2[idx];
    }
    for (int idx = tid; idx < Cc*PIX; idx += 256) {
        int c = idx / PIX, p = idx % PIX;
        xs[idx] = x[(((long)b*Cc + c)*Hh + h)*Ww + w0 + p];
    }
    __syncthreads();

    for (int o = tid; o < Cc; o += 256) {
        float s = 0.f, t = b1[o];
        for (int c = 0; c < Cc; c++) { s += w1[o*Cc + c]; t += p1[o*Cc + c]*nb[c]; }
        s1[o] = s; t1[o] = t;
    }
    for (int p = tid; p < PIX; p += 256) {
        float s = 0.f, q = 0.f;
        for (int c = 0; c < Cc; c++) { float v = xs[c*PIX + p]; s += v; q += v*v; }
        float mu = s * (1.f/Cc);
        float var = q*(1.f/Cc) - mu*mu;
        float r = rsqrtf(var + EPS);
        rval[p] = r; mval[p] = -r*mu;
    }
    __syncthreads();

    const int tx = tid & 15, ty = tid >> 4;
    u64 acc2[4][6];
    float so[4], to[4];
    #pragma unroll
    for (int i = 0; i < 4; i++) { so[i] = s1[ty*4+i]; to[i] = t1[ty*4+i]; }

    #pragma unroll
    for (int i = 0; i < 4; i++)
        #pragma unroll
        for (int j = 0; j < 6; j++) acc2[i][j] = 0ULL;
    for (int c = 0; c < Cc; c++) {
        float4 wv = make_float4(w1[(ty*4+0)*Cc+c], w1[(ty*4+1)*Cc+c],
                                w1[(ty*4+2)*Cc+c], w1[(ty*4+3)*Cc+c]);
        u64 A0 = dup2f(wv.x), A1 = dup2f(wv.y), A2 = dup2f(wv.z), A3 = dup2f(wv.w);
        #pragma unroll
        for (int j = 0; j < 6; j++) {
            u64 X = *(const u64*)&xs[c*PIX + 2*tx + 32*j];
            fma2(acc2[0][j], A0, X); fma2(acc2[1][j], A1, X);
            fma2(acc2[2][j], A2, X); fma2(acc2[3][j], A3, X);
        }
    }
    #pragma unroll
    for (int j = 0; j < 6; j++) {
        int p = 2*tx + 32*j;
        float2 f0 = up2(acc2[0][j]), f1 = up2(acc2[1][j]);
        float2 f2 = up2(acc2[2][j]), f3 = up2(acc2[3][j]);
        float r0 = rval[p], m0 = mval[p], r1 = rval[p+1], m1 = mval[p+1];
        *(uint2*)&b_Q[side][bh][w0+p][ty*4] =
            pack4bf(r0*f0.x + m0*so[0] + to[0], r0*f1.x + m0*so[1] + to[1],
                    r0*f2.x + m0*so[2] + to[2], r0*f3.x + m0*so[3] + to[3]);
        *(uint2*)&b_Q[side][bh][w0+p+1][ty*4] =
            pack4bf(r1*f0.y + m1*so[0] + to[0], r1*f1.y + m1*so[1] + to[1],
                    r1*f2.y + m1*so[2] + to[2], r1*f3.y + m1*so[3] + to[3]);
    }

    #pragma unroll
    for (int i = 0; i < 4; i++)
        #pragma unroll
        for (int j = 0; j < 6; j++) acc2[i][j] = 0ULL;
    for (int c = 0; c < Cc; c++) {
        float4 wv = make_float4(w2[(ty*4+0)*Cc+c], w2[(ty*4+1)*Cc+c],
                                w2[(ty*4+2)*Cc+c], w2[(ty*4+3)*Cc+c]);
        u64 A0 = dup2f(wv.x), A1 = dup2f(wv.y), A2 = dup2f(wv.z), A3 = dup2f(wv.w);
        #pragma unroll
        for (int j = 0; j < 6; j++) {
            u64 X = *(const u64*)&xs[c*PIX + 2*tx + 32*j];
            fma2(acc2[0][j], A0, X); fma2(acc2[1][j], A1, X);
            fma2(acc2[2][j], A2, X); fma2(acc2[3][j], A3, X);
        }
    }
    float bo[4] = {b2[ty*4], b2[ty*4+1], b2[ty*4+2], b2[ty*4+3]};
    #pragma unroll
    for (int j = 0; j < 6; j++) {
        int p = 2*tx + 32*j;
        #pragma unroll
        for (int i = 0; i < 4; i++) {
            float2 f = up2(acc2[i][j]);
            __nv_bfloat162 pr = __floats2bfloat162_rn(f.x + bo[i], f.y + bo[i]);
            *(__nv_bfloat162*)&b_VT[side][bh][ty*4+i][w0+p] = pr;
        }
    }
}

// ================= MMA helpers =================
#define APAD 40
#define APAD2 72
__device__ __forceinline__ void ldsm4(u32& r0, u32& r1, u32& r2, u32& r3, u32 addr) {
    asm volatile("ldmatrix.sync.aligned.m8n8.x4.shared.b16 {%0,%1,%2,%3}, [%4];"
                 : "=r"(r0), "=r"(r1), "=r"(r2), "=r"(r3) : "r"(addr));
}
__device__ __forceinline__ void mma_bf16(float* c, const u32* a, u32 b0, u32 b1) {
    asm volatile("mma.sync.aligned.m16n8k16.row.col.f32.bf16.bf16.f32 "
                 "{%0,%1,%2,%3}, {%4,%5,%6,%7}, {%8,%9}, {%0,%1,%2,%3};"
                 : "+f"(c[0]), "+f"(c[1]), "+f"(c[2]), "+f"(c[3])
                 : "r"(a[0]), "r"(a[1]), "r"(a[2]), "r"(a[3]), "r"(b0), "r"(b1));
}

// ================= K2: attention logits via warp MMA -> bf16 A =================
__global__ void __launch_bounds__(256) k2_attn_mma()
{
    __shared__ __align__(16) __nv_bfloat16 As[128][APAD];
    __shared__ __align__(16) __nv_bfloat16 Bs[128][APAD];
    const int bh = blockIdx.z;
    const int v0 = blockIdx.x * 128, w0 = blockIdx.y * 128;
    const int tid = threadIdx.x, wid = tid >> 5, lane = tid & 31;
    const int wm = wid >> 2, wn = wid & 3;
    const __nv_bfloat16* __restrict__ Ag = &b_Q[0][bh][w0][0];
    const __nv_bfloat16* __restrict__ Bg = &b_Q[1][bh][v0][0];

    float c[4][4][4];
    #pragma unroll
    for (int mt = 0; mt < 4; mt++)
        #pragma unroll
        for (int nt = 0; nt < 4; nt++)
            #pragma unroll
            for (int i = 0; i < 4; i++) c[mt][nt][i] = 0.f;

    const u32 a_base = smem_u32(As), b_base = smem_u32(Bs);
    const u32 a_row = wm*64 + (lane & 15);
    const u32 a_coff = (lane >> 4) * 16;
    const u32 b_row = wn*32 + (lane & 7) + ((lane >> 4) << 3);
    const u32 b_coff = ((lane >> 3) & 1) * 16;

    for (int ch = 0; ch < 2; ch++) {
        #pragma unroll
        for (int p = 0; p < 2; p++) {
            int idx = tid + p*256;
            int row = idx >> 2, seg = idx & 3;
            const int go = row*Cc + ch*32 + seg*8;
            uint4 va = *(const uint4*)(Ag + go);
            uint4 vb = *(const uint4*)(Bg + go);
            *(uint2*)&As[row][seg*8]     = make_uint2(va.x, va.y);
            *(uint2*)&As[row][seg*8 + 4] = make_uint2(va.z, va.w);
            *(uint2*)&Bs[row][seg*8]     = make_uint2(vb.x, vb.y);
            *(uint2*)&Bs[row][seg*8 + 4] = make_uint2(vb.z, vb.w);
        }
        __syncthreads();
        #pragma unroll
        for (int ks = 0; ks < 2; ks++) {
            const u32 kb = ks*32;
            u32 bf[2][4];
            #pragma unroll
            for (int hgrp = 0; hgrp < 2; hgrp++) {
                u32 addr = b_base + (b_row + hgrp*16)*(APAD*2) + kb + b_coff;
                ldsm4(bf[hgrp][0], bf[hgrp][1], bf[hgrp][2], bf[hgrp][3], addr);
            }
            #pragma unroll
            for (int mt = 0; mt < 4; mt++) {
                u32 a[4];
                u32 addr = a_base + (a_row + mt*16)*(APAD*2) + kb + a_coff;
                ldsm4(a[0], a[1], a[2], a[3], addr);
                #pragma unroll
                for (int nt = 0; nt < 4; nt++)
                    mma_bf16(c[mt][nt], a, bf[nt >> 1][(nt & 1)*2], bf[nt >> 1][(nt & 1)*2 + 1]);
            }
        }
        __syncthreads();
    }

    const float s = 0.125f;
    #pragma unroll
    for (int mt = 0; mt < 4; mt++) {
        #pragma unroll
        for (int hh = 0; hh < 2; hh++) {
            int w = w0 + wm*64 + mt*16 + (lane >> 2) + hh*8;
            #pragma unroll
            for (int nt = 0; nt < 4; nt++) {
                int v = v0 + wn*32 + nt*8 + (lane & 3)*2;
                __nv_bfloat162 o = __floats2bfloat162_rn(c[mt][nt][hh*2]*s, c[mt][nt][hh*2+1]*s);
                *(__nv_bfloat162*)&b_A[bh][w][v] = o;
            }
        }
    }
}

// ================= K3a: row stats =================
__global__ void k3a_rowstats()
{
    const int bh = blockIdx.y;
    const int w = blockIdx.x*8 + (threadIdx.x >> 5);
    const int lane = threadIdx.x & 31;
    const __nv_bfloat16* __restrict__ row = b_A[bh][w];
    float f[3][4];
    #pragma unroll
    for (int t = 0; t < 3; t++)
        unp4(*(const uint2*)(row + lane*4 + t*128), f[t]);
    float m = -1e30f;
    #pragma unroll
    for (int t = 0; t < 3; t++)
        #pragma unroll
        for (int e = 0; e < 4; e++) m = fmaxf(m, f[t][e]);
    #pragma unroll
    for (int o = 16; o; o >>= 1) m = fmaxf(m, __shfl_xor_sync(0xffffffffu, m, o));
    float s = 0.f;
    #pragma unroll
    for (int t = 0; t < 3; t++)
        #pragma unroll
        for (int e = 0; e < 4; e++) s += __expf(f[t][e] - m);
    #pragma unroll
    for (int o = 16; o; o >>= 1) s += __shfl_xor_sync(0xffffffffu, s, o);
    if (!lane) { g_rmax[bh][w] = m; g_rinv[bh][w] = 1.f/s; }
}

// ================= K3b: col stats + ms_r2l =================
__global__ void __launch_bounds__(256) k3b_colstats()
{
    __shared__ float sRm[Ww], sRi[Ww];
    __shared__ float red[3][16][16];
    const int bh = blockIdx.y;
    const int tid = threadIdx.x;
    const int lane = tid & 15, grp = tid >> 4;
    const int v = blockIdx.x*16 + lane;

    for (int i = tid; i < Ww; i += 256) { sRm[i] = g_rmax[bh][i]; sRi[i] = g_rinv[bh][i]; }

    float a[24];
    #pragma unroll
    for (int t = 0; t < 24; t++) a[t] = __bfloat162float(b_A[bh][grp + 16*t][v]);
    __syncthreads();

    float m = -1e30f;
    #pragma unroll
    for (int t = 0; t < 24; t++) m = fmaxf(m, a[t]);
    red[0][grp][lane] = m;
    __syncthreads();
    if (grp == 0) {
        for (int k = 1; k < 16; k++) m = fmaxf(m, red[0][k][lane]);
        red[0][0][lane] = m;
    }
    __syncthreads();
    m = red[0][0][lane];

    float s = 0.f, ms = 0.f;
    #pragma unroll
    for (int t = 0; t < 24; t++) {
        int row = grp + 16*t;
        s  += __expf(a[t] - m);
        ms += __expf(a[t] - sRm[row]) * sRi[row];
    }
    red[1][grp][lane] = s; red[2][grp][lane] = ms;
    __syncthreads();
    if (grp == 0) {
        for (int k = 1; k < 16; k++) { s += red[1][k][lane]; ms += red[2][k][lane]; }
        g_cmax[bh][v] = m;
        g_cinv[bh][v] = 1.f/s;
        g_ms_r2l[bh][v] = ms;
    }
}

// ================= K4: bf16 M matrices in both orientations =================
__global__ void __launch_bounds__(256) k4_writeM()
{
    __shared__ __align__(16) __nv_bfloat16 s1[64][68];
    __shared__ __align__(16) __nv_bfloat16 s2[64][68];
    const int bh = blockIdx.y;
    const int u0 = blockIdx.x*64;
    const int tid = threadIdx.x;
    const int row = tid >> 2, seg = tid & 3;
    const int u = u0 + row;
    const float rm = g_rmax[bh][u], ri = g_rinv[bh][u];
    float msum = 0.f;

    for (int ct = 0; ct < 6; ct++) {
        const int c0 = ct*64 + seg*16;
        #pragma unroll
        for (int q = 0; q < 4; q++) {
            int v = c0 + q*4;
            float a[4];
            unp4(*(const uint2*)&b_A[bh][u][v], a);
            float4 cm = *(const float4*)&g_cmax[bh][v];
            float4 ci = *(const float4*)&g_cinv[bh][v];
            float4 m1 = make_float4(__expf(a[0]-rm)*ri, __expf(a[1]-rm)*ri,
                                    __expf(a[2]-rm)*ri, __expf(a[3]-rm)*ri);
            float4 m2 = make_float4(__expf(a[0]-cm.x)*ci.x, __expf(a[1]-cm.y)*ci.y,
                                    __expf(a[2]-cm.z)*ci.z, __expf(a[3]-cm.w)*ci.w);
            uint2 p1 = pack4bf(m1.x, m1.y, m1.z, m1.w);
            uint2 p2 = pack4bf(m2.x, m2.y, m2.z, m2.w);
            *(uint2*)&b_Mr2l[bh][u][v] = p1;
            *(uint2*)&b_MLT[bh][u][v]  = p2;
            *(uint2*)&s1[row][seg*16 + q*4] = p1;
            *(uint2*)&s2[row][seg*16 + q*4] = p2;
            msum += m2.x + m2.y + m2.z + m2.w;
        }
        __syncthreads();
        {
            const int vl = row;
            const u16* p1r = (const u16*)s1;
            const u16* p2r = (const u16*)s2;
            #pragma unroll
            for (int q = 0; q < 4; q++) {
                int ub = seg*16 + q*4;
                uint2 o1, o2;
                o1.x = (u32)p1r[(ub+0)*68 + vl] | ((u32)p1r[(ub+1)*68 + vl] << 16);
                o1.y = (u32)p1r[(ub+2)*68 + vl] | ((u32)p1r[(ub+3)*68 + vl] << 16);
                o2.x = (u32)p2r[(ub+0)*68 + vl] | ((u32)p2r[(ub+1)*68 + vl] << 16);
                o2.y = (u32)p2r[(ub+2)*68 + vl] | ((u32)p2r[(ub+3)*68 + vl] << 16);
                *(uint2*)&b_Mr2lT[bh][ct*64 + vl][u0 + ub] = o1;
                *(uint2*)&b_MLTT[bh][ct*64 + vl][u0 + ub]  = o2;
            }
        }
        __syncthreads();
    }
    msum += __shfl_xor_sync(0xffffffffu, msum, 1);
    msum += __shfl_xor_sync(0xffffffffu, msum, 2);
    if (seg == 0) g_ms_l2r[bh][u] = msum;
}

// ================= K5: cycle loss via warp MMA, k-chunk 64 (static smem) =================
__global__ void __launch_bounds__(256) k5_cycle_mma()
{
    __shared__ __align__(16) __nv_bfloat16 As[128][APAD2];
    __shared__ __align__(16) __nv_bfloat16 Bs[128][APAD2];
    __shared__ float red[256];
    const int z = blockIdx.z, term = z & 1, bh = z >> 1;
    const int u0 = blockIdx.x*128, w0 = blockIdx.y*128;
    const int tid = threadIdx.x, wid = tid >> 5, lane = tid & 31;
    const int wm = wid >> 2, wn = wid & 3;
    const __nv_bfloat16* __restrict__ Ag = term == 0 ? &b_Mr2l[bh][w0][0] : &b_MLTT[bh][w0][0];
    const __nv_bfloat16* __restrict__ Bg = term == 0 ? &b_MLT[bh][u0][0]  : &b_Mr2lT[bh][u0][0];

    float c[4][4][4];
    #pragma unroll
    for (int mt = 0; mt < 4; mt++)
        #pragma unroll
        for (int nt = 0; nt < 4; nt++)
            #pragma unroll
            for (int i = 0; i < 4; i++) c[mt][nt][i] = 0.f;

    const u32 a_base = smem_u32(As), b_base = smem_u32(Bs);
    const u32 a_row = wm*64 + (lane & 15);
    const u32 a_coff = (lane >> 4) * 16;
    const u32 b_row = wn*32 + (lane & 7) + ((lane >> 4) << 3);
    const u32 b_coff = ((lane >> 3) & 1) * 16;

    for (int ch = 0; ch < 6; ch++) {
        #pragma unroll
        for (int p = 0; p < 4; p++) {
            int idx = tid + p*256;
            int row = idx >> 3, seg = idx & 7;
            const long go = (long)row*Ww + ch*64 + seg*8;
            uint4 va = *(const uint4*)(Ag + go);
            uint4 vb = *(const uint4*)(Bg + go);
            *(uint2*)&As[row][seg*8]     = make_uint2(va.x, va.y);
            *(uint2*)&As[row][seg*8 + 4] = make_uint2(va.z, va.w);
            *(uint2*)&Bs[row][seg*8]     = make_uint2(vb.x, vb.y);
            *(uint2*)&Bs[row][seg*8 + 4] = make_uint2(vb.z, vb.w);
        }
        __syncthreads();
        #pragma unroll
        for (int ks = 0; ks < 4; ks++) {
            const u32 kb = ks*32;
            u32 bf[2][4];
            #pragma unroll
            for (int hgrp = 0; hgrp < 2; hgrp++) {
                u32 addr = b_base + (b_row + hgrp*16)*(APAD2*2) + kb + b_coff;
                ldsm4(bf[hgrp][0], bf[hgrp][1], bf[hgrp][2], bf[hgrp][3], addr);
            }
            #pragma unroll
            for (int mt = 0; mt < 4; mt++) {
                u32 a[4];
                u32 addr = a_base + (a_row + mt*16)*(APAD2*2) + kb + a_coff;
                ldsm4(a[0], a[1], a[2], a[3], addr);
                #pragma unroll
                for (int nt = 0; nt < 4; nt++)
                    mma_bf16(c[mt][nt], a, bf[nt >> 1][(nt & 1)*2], bf[nt >> 1][(nt & 1)*2 + 1]);
            }
        }
        __syncthreads();
    }

    const float* __restrict__ msrow = (term == 0) ? g_ms_l2r[bh] : g_ms_r2l[bh];
    float lsum = 0.f;
    #pragma unroll
    for (int nt = 0; nt < 4; nt++) {
        #pragma unroll
        for (int jj = 0; jj < 2; jj++) {
            int u = u0 + wn*32 + nt*8 + (lane & 3)*2 + jj;
            float mk = (msrow[u] > 0.1f) ? 1.f : 0.f;
            #pragma unroll
            for (int mt = 0; mt < 4; mt++) {
                #pragma unroll
                for (int hh = 0; hh < 2; hh++) {
                    int w = w0 + wm*64 + mt*16 + (lane >> 2) + hh*8;
                    float dv = c[mt][nt][hh*2 + jj];
                    lsum += mk * fabsf(dv - ((w == u) ? 1.f : 0.f));
                }
            }
        }
    }
    red[tid] = lsum; __syncthreads();
    for (int s = 128; s; s >>= 1) { if (tid < s) red[tid] += red[tid+s]; __syncthreads(); }
    if (!tid) g_p_cyc[z*9 + blockIdx.y*3 + blockIdx.x] = red[0];
}

// ================= K6: outputs via warp MMA, both sides in one launch =================
__global__ void __launch_bounds__(256) k6_mma(const float* __restrict__ x_l,
                                              const float* __restrict__ x_r,
                                              const float* __restrict__ beta,
                                              const float* __restrict__ gamma,
                                              float* __restrict__ out_xl,
                                              float* __restrict__ out_xr)
{
    __shared__ __align__(16) __nv_bfloat16 As[128][APAD];
    __shared__ __align__(16) __nv_bfloat16 Bs[64][APAD];
    const int side = blockIdx.z;
    const float* __restrict__ x  = side ? x_r : x_l;
    const float* __restrict__ bg = side ? gamma : beta;
    float* __restrict__ out = side ? out_xr : out_xl;
    const int bh = blockIdx.y;
    const int b = bh / Hh, h = bh % Hh;
    const int w0 = blockIdx.x * 128;
    const int tid = threadIdx.x, wid = tid >> 5, lane = tid & 31;
    const int wm = wid >> 2, wn = wid & 3;
    const __nv_bfloat16* __restrict__ Ag = side == 0 ? &b_Mr2l[bh][w0][0] : &b_MLTT[bh][w0][0];
    const __nv_bfloat16* __restrict__ Bg = &b_VT[side == 0 ? 1 : 0][bh][0][0];

    float c[4][2][4];
    #pragma unroll
    for (int mt = 0; mt < 4; mt++)
        #pragma unroll
        for (int nt = 0; nt < 2; nt++)
            #pragma unroll
            for (int i = 0; i < 4; i++) c[mt][nt][i] = 0.f;

    const u32 a_base = smem_u32(As), b_base = smem_u32(Bs);
    const u32 a_row = wm*64 + (lane & 15);
    const u32 a_coff = (lane >> 4) * 16;
    const u32 b_row = wn*16 + (lane & 7) + ((lane >> 4) << 3);
    const u32 b_coff = ((lane >> 3) & 1) * 16;

    for (int ch = 0; ch < 12; ch++) {
        #pragma unroll
        for (int p = 0; p < 2; p++) {
            int idx = tid + p*256;
            int row = idx >> 2, seg = idx & 3;
            uint4 va = *(const uint4*)(Ag + (long)row*Ww + ch*32 + seg*8);
            *(uint2*)&As[row][seg*8]     = make_uint2(va.x, va.y);
            *(uint2*)&As[row][seg*8 + 4] = make_uint2(va.z, va.w);
        }
        {
            int row = tid >> 2, seg = tid & 3;
            uint4 vb = *(const uint4*)(Bg + (long)row*Ww + ch*32 + seg*8);
            *(uint2*)&Bs[row][seg*8]     = make_uint2(vb.x, vb.y);
            *(uint2*)&Bs[row][seg*8 + 4] = make_uint2(vb.z, vb.w);
        }
        __syncthreads();
        #pragma unroll
        for (int ks = 0; ks < 2; ks++) {
            const u32 kb = ks*32;
            u32 bfr[4];
            ldsm4(bfr[0], bfr[1], bfr[2], bfr[3], b_base + b_row*(APAD*2) + kb + b_coff);
            #pragma unroll
            for (int mt = 0; mt < 4; mt++) {
                u32 a[4];
                ldsm4(a[0], a[1], a[2], a[3], a_base + (a_row + mt*16)*(APAD*2) + kb + a_coff);
                mma_bf16(c[mt][0], a, bfr[0], bfr[1]);
                mma_bf16(c[mt][1], a, bfr[2], bfr[3]);
            }
        }
        __syncthreads();
    }

    #pragma unroll
    for (int nt = 0; nt < 2; nt++) {
        #pragma unroll
        for (int jj = 0; jj < 2; jj++) {
            int cc = wn*16 + nt*8 + (lane & 3)*2 + jj;
            float bgc = bg[cc];
            #pragma unroll
            for (int mt = 0; mt < 4; mt++) {
                #pragma unroll
                for (int hh = 0; hh < 2; hh++) {
                    int w = w0 + wm*64 + mt*16 + (lane >> 2) + hh*8;
                    long gi = (((long)b*Cc + cc)*Hh + h)*Ww + w;
                    out[gi] = x[gi] + bgc * c[mt][nt][hh*2 + jj];
                }
            }
        }
    }
}

// ================= K7a: photo term 1 =================
__global__ void k7a_photo1(const float* __restrict__ LRl, const float* __restrict__ LRr)
{
    __shared__ float lr[3][Ww];
    __shared__ float r8[8];
    const int bh = blockIdx.y;
    const int b = bh / Hh, h = bh % Hh;
    const int w = blockIdx.x*8 + (threadIdx.x >> 5);
    const int lane = threadIdx.x & 31;
    for (int idx = threadIdx.x; idx < 3*Ww; idx += 256) {
        int ch = idx / Ww, v = idx % Ww;
        lr[ch][v] = LRr[(((long)b*3 + ch)*Hh + h)*Ww + v];
    }
    __syncthreads();
    float a0 = 0.f, a1 = 0.f, a2 = 0.f;
    const __nv_bfloat16* __restrict__ mrow = b_Mr2l[bh][w];
    #pragma unroll
    for (int t = 0; t < 3; t++) {
        int v4 = lane*4 + t*128;
        uint2 pk = *(const uint2*)(mrow + v4);
        float f[4]; unp4(pk, f);
        #pragma unroll
        for (int e = 0; e < 4; e++) {
            a0 += f[e]*lr[0][v4+e]; a1 += f[e]*lr[1][v4+e]; a2 += f[e]*lr[2][v4+e];
        }
    }
    #pragma unroll
    for (int o = 16; o; o >>= 1) {
        a0 += __shfl_xor_sync(0xffffffffu, a0, o);
        a1 += __shfl_xor_sync(0xffffffffu, a1, o);
        a2 += __shfl_xor_sync(0xffffffffu, a2, o);
    }
    if (!lane) {
        float mk = (g_ms_l2r[bh][w] > 0.1f) ? 1.f : 0.f;
        long base = (((long)b*3)*Hh + h)*Ww + w;
        float part = mk * (fabsf(LRl[base] - a0)
                         + fabsf(LRl[base + (long)Hh*Ww] - a1)
                         + fabsf(LRl[base + 2L*Hh*Ww] - a2));
        r8[threadIdx.x >> 5] = part;
    }
    __syncthreads();
    if (threadIdx.x == 0) {
        float s = 0.f;
        for (int k = 0; k < 8; k++) s += r8[k];
        g_p_ph1[bh*48 + blockIdx.x] = s;
    }
}

// ================= K7b: photo term 2 =================
__global__ void k7b_photo2(const float* __restrict__ LRl, const float* __restrict__ LRr)
{
    __shared__ float la[3][Ww], lb[3][Ww];
    __shared__ float red[128];
    const int bh = blockIdx.x;
    const int b = bh / Hh, h = bh % Hh;
    const int tid = threadIdx.x;
    for (int idx = tid; idx < 3*Ww; idx += 128) {
        int ch = idx / Ww, w = idx % Ww;
        long gi = (((long)b*3 + ch)*Hh + h)*Ww + w;
        la[ch][w] = LRl[gi];
        lb[ch][w] = LRr[gi];
    }
    __syncthreads();
    float acc[3][3] = {};
    for (int v = 0; v < Ww; v++) {
        const __nv_bfloat16* __restrict__ mr = b_MLT[bh][v];
        float l0 = la[0][v], l1 = la[1][v], l2 = la[2][v];
        #pragma unroll
        for (int s = 0; s < 3; s++) {
            float m = __bfloat162float(mr[tid + s*128]);
            acc[s][0] += m*l0; acc[s][1] += m*l1; acc[s][2] += m*l2;
        }
    }
    float part = 0.f;
    #pragma unroll
    for (int s = 0; s < 3; s++) {
        int w = tid + s*128;
        float mk = (g_ms_r2l[bh][w] > 0.1f) ? 1.f : 0.f;
        part += mk * (fabsf(lb[0][w] - acc[s][0])
                    + fabsf(lb[1][w] - acc[s][1])
                    + fabsf(lb[2][w] - acc[s][2]));
    }
    red[tid] = part; __syncthreads();
    for (int s = 64; s; s >>= 1) { if (tid < s) red[tid] += red[tid+s]; __syncthreads(); }
    if (!tid) g_p_ph2[bh] = red[0];
}

// ================= K8: smoothness =================
__global__ void k8_smooth()
{
    __shared__ float redh[256], redw[256];
    const int mat = blockIdx.z, bh = blockIdx.y, w0 = blockIdx.x*16;
    const int h = bh % Hh;
    const __nv_bfloat16* __restrict__ M = mat ? &b_MLT[0][0][0] : &b_Mr2l[0][0][0];
    const int tid = threadIdx.x;
    const bool hok = (h < Hh - 1);
    float sh = 0.f, sw = 0.f;
    for (int i = tid; i < 16*96; i += 256) {
        int w = w0 + i/96, v4 = (i%96)*4;
        long base = ((long)bh*Ww + w)*Ww + v4;
        float cv[4]; unp4(*(const uint2*)(M + base), cv);
        if (hok) {
            float nh[4]; unp4(*(const uint2*)(M + base + (long)Ww*Ww), nh);
            sh += fabsf(cv[0]-nh[0]) + fabsf(cv[1]-nh[1])
                + fabsf(cv[2]-nh[2]) + fabsf(cv[3]-nh[3]);
        }
        if (w < Ww - 1) {
            float nr[4]; unp4(*(const uint2*)(M + base + Ww), nr);
            sw += fabsf(cv[0]-nr[1]) + fabsf(cv[1]-nr[2]) + fabsf(cv[2]-nr[3]);
            if (v4 < 380) {
                float n4 = __bfloat162float(M[base + Ww + 4]);
                sw += fabsf(cv[3] - n4);
            }
        }
    }
    redh[tid] = sh; redw[tid] = sw; __syncthreads();
    for (int s = 128; s; s >>= 1) {
        if (tid < s) { redh[tid] += redh[tid+s]; redw[tid] += redw[tid+s]; }
        __syncthreads();
    }
    if (!tid) {
        int slot = (mat*BHn + bh)*24 + blockIdx.x;
        g_p_smh[slot] = redh[0];
        g_p_smw[slot] = redw[0];
    }
}

// ================= K9 =================
__global__ void k9_final(const float* __restrict__ loss_in, float* __restrict__ out_loss)
{
    __shared__ double red[256];
    const int tid = threadIdx.x;
    double acc[4] = {0.0, 0.0, 0.0, 0.0};
    for (int i = tid; i < NP_CYC; i += 256) acc[0] += (double)g_p_cyc[i];
    for (int i = tid; i < NP_PH1; i += 256) acc[1] += (double)g_p_ph1[i];
    for (int i = tid; i < NP_PH2; i += 256) acc[1] += (double)g_p_ph2[i];
    for (int i = tid; i < NP_SM;  i += 256) acc[2] += (double)g_p_smh[i];
    for (int i = tid; i < NP_SM;  i += 256) acc[3] += (double)g_p_smw[i];
    double tot[4];
    for (int a = 0; a < 4; a++) {
        red[tid] = acc[a]; __syncthreads();
        for (int s = 128; s; s >>= 1) { if (tid < s) red[tid] += red[tid+s]; __syncthreads(); }
        tot[a] = red[0]; __syncthreads();
    }
    if (!tid) {
        double lc = tot[0] / ((double)Bz*Hh*Ww*Ww);
        double lp = tot[1] / ((double)Bz*3*Hh*Ww);
        double lh = tot[2] / ((double)Bz*(Hh-1)*Ww*Ww);
        double lw = tot[3] / ((double)Bz*Hh*(Ww-1)*(Ww-1));
        out_loss[0] = (float)((double)loss_in[0] + 0.0025*(lp + 0.1*(lw + lh) + lc));
    }
}

extern "C" void kernel_launch(void* const* d_in, const int* in_sizes, int n_in,
                              void* d_out, int out_size)
{
    (void)in_sizes; (void)n_in; (void)out_size;
    const float* x_l   = (const float*)d_in[0];
    const float* x_r   = (const float*)d_in[1];
    const float* LRl   = (const float*)d_in[2];
    const float* LRr   = (const float*)d_in[3];
    const float* lossi = (const float*)d_in[4];
    const float* nlw = (const float*)d_in[5];
    const float* nlb = (const float*)d_in[6];
    const float* nrw = (const float*)d_in[7];
    const float* nrb = (const float*)d_in[8];
    const float* lp1w = (const float*)d_in[9];
    const float* lp1b = (const float*)d_in[10];
    const float* rp1w = (const float*)d_in[11];
    const float* rp1b = (const float*)d_in[12];
    const float* lp2w = (const float*)d_in[13];
    const float* lp2b = (const float*)d_in[14];
    const float* rp2w = (const float*)d_in[15];
    const float* rp2b = (const float*)d_in[16];
    const float* beta  = (const float*)d_in[17];
    const float* gamma = (const float*)d_in[18];

    float* out = (float*)d_out;
    float* out_xl   = out;
    float* out_xr   = out + NX;
    float* out_lrl  = out + 2L*NX;
    float* out_lrr  = out + 2L*NX + NLR;
    float* out_loss = out + 2L*NX + 2L*NLR;

    const size_t smem1 = (size_t)(Cc*PIX + 2*Cc*Cc + 2*Cc + 2*PIX) * sizeof(float);
    cudaFuncSetAttribute(k1_lnproj, cudaFuncAttributeMaxDynamicSharedMemorySize, (int)smem1);

    k1_lnproj<<<dim3(2, BHn, 2), 256, smem1>>>(x_l, x_r, nlw, nlb, nrw, nrb,
                                               lp1w, lp1b, rp1w, rp1b,
                                               lp2w, lp2b, rp2w, rp2b);
    k2_attn_mma<<<dim3(3, 3, BHn), 256>>>();
    k3a_rowstats<<<dim3(48, BHn), 256>>>();
    k3b_colstats<<<dim3(24, BHn), 256>>>();
    k4_writeM<<<dim3(6, BHn), 256>>>();
    k5_cycle_mma<<<dim3(3, 3, BHn*2), 256>>>();
    k6_mma<<<dim3(3, BHn, 2), 256>>>(x_l, x_r, beta, gamma, out_xl, out_xr);
    k7a_photo1<<<dim3(48, BHn), 256>>>(LRl, LRr);
    k7b_photo2<<<BHn, 128>>>(LRl, LRr);
    k8_smooth<<<dim3(24, BHn, 2), 256>>>();
    cudaMemcpyAsync(out_lrl, LRl, (size_t)NLR*sizeof(float), cudaMemcpyDeviceToDevice, 0);
    cudaMemcpyAsync(out_lrr, LRr, (size_t)NLR*sizeof(float), cudaMemcpyDeviceToDevice, 0);
    k9_final<<<1, 256>>>(lossi, out_loss);
}